// round 14
// baseline (speedup 1.0000x reference)
#include <cuda_runtime.h>
#include <math.h>

#define IMW 1024
#define IMH 1024
#define NB 4
#define NQ 262144      // queries per batch (2^18)
#define DCAP 46        // distances >= 46 all map to weight 1.0
#define NPIX ((size_t)NB * IMH * IMW)

// Scratch (device globals — no allocation allowed). uint4 type guarantees 16B alignment.
__device__ uint4 g_h4[NPIX / 16];   // row nearest-zero distances, 1 byte/px
__device__ uint4 g_p4[NPIX / 4];    // packed 4B records: depth f32, low 6 mantissa bits = (code<<1)|edge

// movemask of "pixel == 0.0f" for 4 packed float words (values are exactly 0.0f or 1.0f)
__device__ __forceinline__ unsigned int movemask_zero4(unsigned int x, unsigned int y,
                                                       unsigned int z, unsigned int w) {
    const unsigned int t01 = __byte_perm(x, y, 0x0073);      // [x.b3, y.b3, ., .]
    const unsigned int t23 = __byte_perm(z, w, 0x0073);      // [z.b3, w.b3, ., .]
    const unsigned int tops = __byte_perm(t01, t23, 0x5410); // [x.b3,y.b3,z.b3,w.b3]
    // 1.0f top byte = 0x3F (bit5=1); 0.0f -> 0x00 (bit5=0)
    const unsigned int u = (~tops) & 0x20202020u;            // 0x20 per zero pixel
    return ((u >> 5) * 0x01020408u) >> 24;                   // 4-bit movemask (bit k <-> px k)
}

// ---------------------------------------------------------------------------
// Kernel 1: per-row 1D distance to nearest zero, capped at DCAP.
// 2 warps per row, 16 px/thread (2x the thread count of the 32 px/thread
// version -> occupancy ~86% theoretical vs 43%). Coalesced uint4 loads +
// shfl transpose build a 16-bit flag word per thread; the full 1024-bit row
// bitmap goes to smem (32 uints) so windows can cross the half-row seam.
// 64-bit R/L windows cover DCAP fully -> exact, no fallback path:
//   h(px p+j) = ffsll( (R>>j) | (L>>(15-j)) ) - 1.
// ---------------------------------------------------------------------------
__global__ void row_dist_kernel(const uint4* __restrict__ mask4) {
    __shared__ unsigned int rb[4][32];                 // 4 rows/block, 1024-bit bitmaps
    const int t = threadIdx.x;
    const int lane = t & 31;
    const int half = (t >> 5) & 1;                     // which half-row this warp owns
    const int rowblk = t >> 6;                         // row within block (0..3)
    const int row = blockIdx.x * 4 + rowblk;           // 0 .. NB*IMH-1
    const uint4* mrow = mask4 + (size_t)row * 256 + half * 128;

    // Coalesced flag build: thread reads uint4 k*32+lane of its half-row.
    unsigned int nw = 0;
    #pragma unroll
    for (int k = 0; k < 4; ++k) {
        const uint4 v = mrow[k * 32 + lane];
        nw |= movemask_zero4(v.x, v.y, v.z, v.w) << (4 * k);
    }

    // Transpose: thread t needs nibbles of uint4s 4t..4t+3 (source lane
    // (t&7)*4+m, slot t>>3 constant per thread).
    const int srcbase = (lane & 7) * 4;
    const int slotsh = (lane >> 3) * 4;
    unsigned int w16 = 0;
    #pragma unroll
    for (int m = 0; m < 4; ++m) {
        const unsigned int xm = __shfl_sync(~0u, nw, srcbase + m);
        w16 |= ((xm >> slotsh) & 0xFu) << (4 * m);
    }

    // Publish row bitmap: pair adjacent threads' 16-bit words into uints.
    const unsigned int up = __shfl_down_sync(~0u, w16, 1);
    if (!(lane & 1)) rb[rowblk][half * 16 + (lane >> 1)] = w16 | (up << 16);
    __syncthreads();

    // Assemble 64-bit windows for this thread's 16 pixels (p = 16*I16).
    const int I16 = half * 32 + lane;                  // 16-bit-word index in row (0..63)
    const int wi = I16 >> 1;
    const unsigned int* rw = rb[rowblk];
    const unsigned int u0  = rw[wi];
    const unsigned int u1  = (wi + 1 < 32) ? rw[wi + 1] : 0u;
    const unsigned int u2  = (wi + 2 < 32) ? rw[wi + 2] : 0u;
    const unsigned int vm1 = (wi >= 1) ? rw[wi - 1] : 0u;
    const unsigned int vm2 = (wi >= 2) ? rw[wi - 2] : 0u;

    // R bit b = flag[p+b]
    const unsigned long long lo = ((unsigned long long)u1 << 32) | u0;
    unsigned long long R, H;
    if (I16 & 1) {
        R = (lo >> 16) | ((unsigned long long)u2 << 48);
        H = ((unsigned long long)u0 << 32) | vm1;      // H bit b = flag[q-63+b], q=p+15
    } else {
        R = lo;
        H = ((unsigned long long)vm1 << 16) | (vm2 >> 16) | ((unsigned long long)u0 << 48);
    }
    // L bit k = flag[q-k]  (bit-reverse of H)
    const unsigned long long L =
        ((unsigned long long)__brev((unsigned int)H) << 32) | __brev((unsigned int)(H >> 32));

    unsigned int g[4];
    #pragma unroll
    for (int j = 0; j < 16; ++j) {
        const unsigned long long C = (R >> j) | (L >> (15 - j));
        int h = C ? (__ffsll((long long)C) - 1) : DCAP;   // coverage >= 48 > DCAP: exact
        h = min(h, DCAP);
        if ((j & 3) == 0) g[j >> 2] = (unsigned int)h;
        else              g[j >> 2] |= (unsigned int)h << (8 * (j & 3));
    }
    g_h4[(size_t)row * 64 + I16] = make_uint4(g[0], g[1], g[2], g[3]);
}

// ---------------------------------------------------------------------------
// Kernel 2: Chebyshev DT column combine (SIMD bytes) + pack 4B fusion records.
// 8 px/thread. d(x,y) = min_r max(r, min(h[y-r], h[y+r])), early exit.
// ---------------------------------------------------------------------------
__device__ __forceinline__ unsigned int hmax8(unsigned int a, unsigned int b) {
    unsigned int m = __vmaxu4(a, b);
    m = __vmaxu4(m, m >> 16);
    m = __vmaxu4(m, m >> 8);
    return m & 0xFFu;
}

__device__ __forceinline__ unsigned int make_rec(unsigned int dbits, unsigned int ebits,
                                                 unsigned int b8) {
    // code = floor((d+2)/3) in 0..16 (exact via *171>>9 for d<=46); edge bit from f32 0/1
    const unsigned int c = ((b8 + 2u) * 171u) >> 9;
    return ((dbits + 32u) & ~63u) | (c << 1) | ((ebits >> 29) & 1u);
}

__global__ void col_pack_kernel(const uint4* __restrict__ depth4,
                                const uint4* __restrict__ edge4) {
    const int tid = blockIdx.x * blockDim.x + threadIdx.x;   // 0 .. NPIX/8-1
    const int y = (tid >> 7) & (IMH - 1);
    const unsigned long long* gh = (const unsigned long long*)g_h4;
    const size_t cbase = ((size_t)(tid >> 17) << 17) + (tid & 127); // b*131072 + x8

    const unsigned long long hv = gh[tid];
    unsigned int blo = (unsigned int)hv, bhi = (unsigned int)(hv >> 32);
    unsigned int bmax = hmax8(blo, bhi);

    #pragma unroll 1
    for (unsigned int r = 1; r < bmax; ++r) {
        const int yu = y - (int)r;
        const int yd = y + (int)r;
        unsigned int ulo = 0x2E2E2E2Eu, uhi = 0x2E2E2E2Eu;   // DCAP bytes
        if (yu >= 0) {
            const unsigned long long hu = gh[cbase + (size_t)yu * 128];
            ulo = (unsigned int)hu; uhi = (unsigned int)(hu >> 32);
        }
        if (yd < IMH) {
            const unsigned long long hd = gh[cbase + (size_t)yd * 128];
            ulo = __vminu4(ulo, (unsigned int)hd);
            uhi = __vminu4(uhi, (unsigned int)(hd >> 32));
        }
        const unsigned int rq = r * 0x01010101u;
        blo = __vminu4(blo, __vmaxu4(ulo, rq));
        bhi = __vminu4(bhi, __vmaxu4(uhi, rq));
        bmax = hmax8(blo, bhi);
    }

    const uint4 d0 = depth4[tid * 2], d1 = depth4[tid * 2 + 1];
    const uint4 e0 = edge4[tid * 2],  e1 = edge4[tid * 2 + 1];

    uint4 pA, pB;
    pA.x = make_rec(d0.x, e0.x,  blo        & 0xFFu);
    pA.y = make_rec(d0.y, e0.y, (blo >>  8) & 0xFFu);
    pA.z = make_rec(d0.z, e0.z, (blo >> 16) & 0xFFu);
    pA.w = make_rec(d0.w, e0.w,  blo >> 24);
    pB.x = make_rec(d1.x, e1.x,  bhi        & 0xFFu);
    pB.y = make_rec(d1.y, e1.y, (bhi >>  8) & 0xFFu);
    pB.z = make_rec(d1.z, e1.z, (bhi >> 16) & 0xFFu);
    pB.w = make_rec(d1.w, e1.w,  bhi >> 24);
    g_p4[tid * 2]     = pA;
    g_p4[tid * 2 + 1] = pB;
}

// ---------------------------------------------------------------------------
// Kernel 3: fused bilinear sampling + psdf weighting + occupancy fusion.
// 4 queries/thread (float4 I/O, 16 outstanding 4B gathers into 16MB L2 image).
// ---------------------------------------------------------------------------
__device__ __forceinline__ float fuse_one(int b, float px, float py, float zz,
                                          float ob, float of) {
    const unsigned int* __restrict__ gp = (const unsigned int*)g_p4;

    const float gx = (px + 1.0f) * 0.5f * (float)(IMW - 1);
    const float gy = (py + 1.0f) * 0.5f * (float)(IMH - 1);
    const float x0f = floorf(gx);
    const float y0f = floorf(gy);
    const float wx = gx - x0f;
    const float wy = gy - y0f;

    const int x0 = (int)fminf(fmaxf(x0f,        0.0f), (float)(IMW - 1));
    const int x1 = (int)fminf(fmaxf(x0f + 1.0f, 0.0f), (float)(IMW - 1));
    const int y0 = (int)fminf(fmaxf(y0f,        0.0f), (float)(IMH - 1));
    const int y1 = (int)fminf(fmaxf(y0f + 1.0f, 0.0f), (float)(IMH - 1));

    const size_t base = (size_t)b * IMH * IMW;
    const unsigned int u00 = __ldg(&gp[base + (size_t)y0 * IMW + x0]);
    const unsigned int u10 = __ldg(&gp[base + (size_t)y0 * IMW + x1]);
    const unsigned int u01 = __ldg(&gp[base + (size_t)y1 * IMW + x0]);
    const unsigned int u11 = __ldg(&gp[base + (size_t)y1 * IMW + x1]);

    const float w00 = (1.0f - wx) * (1.0f - wy);
    const float w10 = wx * (1.0f - wy);
    const float w01 = (1.0f - wx) * wy;
    const float w11 = wx * wy;

    const float edge = (float)(u00 & 1u) * w00 + (float)(u10 & 1u) * w10
                     + (float)(u01 & 1u) * w01 + (float)(u11 & 1u) * w11;

    const float dq = __uint_as_float(u00 & ~63u) * w00 + __uint_as_float(u10 & ~63u) * w10
                   + __uint_as_float(u01 & ~63u) * w01 + __uint_as_float(u11 & ~63u) * w11;

    const int c00 = (int)((u00 >> 1) & 31u), c10 = (int)((u10 >> 1) & 31u);
    const int c01 = (int)((u01 >> 1) & 31u), c11 = (int)((u11 >> 1) & 31u);
    const float v00 = c00 ? (0.1f + 0.06f * (float)(c00 - 1)) : 0.0f;
    const float v10 = c10 ? (0.1f + 0.06f * (float)(c10 - 1)) : 0.0f;
    const float v01 = c01 ? (0.1f + 0.06f * (float)(c01 - 1)) : 0.0f;
    const float v11 = c11 ? (0.1f + 0.06f * (float)(c11 - 1)) : 0.0f;
    const float lab = v00 * w00 + v10 * w10 + v01 * w01 + v11 * w11;

    const float eb = (edge > 0.01f) ? 1.0f : 0.0f;
    const float psdf = zz - dq * eb;
    const float w = expf(-psdf * psdf * 1000.0f) * lab * eb;
    return w * of + (1.0f - w) * ob;
}

__global__ void fuse_kernel(const float* __restrict__ xy,
                            const float* __restrict__ z,
                            const float* __restrict__ occ_body,
                            const float* __restrict__ occ_face,
                            float* __restrict__ out) {
    const int t = blockIdx.x * blockDim.x + threadIdx.x;     // 0 .. NB*NQ/4-1
    const int i0 = t * 4;
    const int b = i0 >> 18;
    const int n0 = i0 & (NQ - 1);

    const float4 xs = *(const float4*)(xy + (size_t)b * 2 * NQ + n0);
    const float4 ys = *(const float4*)(xy + (size_t)b * 2 * NQ + NQ + n0);
    const float4 zs  = *(const float4*)(z + i0);
    const float4 obs = *(const float4*)(occ_body + i0);
    const float4 ofs = *(const float4*)(occ_face + i0);

    float4 r;
    r.x = fuse_one(b, xs.x, ys.x, zs.x, obs.x, ofs.x);
    r.y = fuse_one(b, xs.y, ys.y, zs.y, obs.y, ofs.y);
    r.z = fuse_one(b, xs.z, ys.z, zs.z, obs.z, ofs.z);
    r.w = fuse_one(b, xs.w, ys.w, zs.w, obs.w, ofs.w);
    *(float4*)(out + i0) = r;
}

// ---------------------------------------------------------------------------
extern "C" void kernel_launch(void* const* d_in, const int* in_sizes, int n_in,
                              void* d_out, int out_size) {
    const float* mask       = (const float*)d_in[0];
    const float* face_depth = (const float*)d_in[1];
    const float* edge_mask  = (const float*)d_in[2];
    const float* xy         = (const float*)d_in[3];
    const float* z          = (const float*)d_in[4];
    const float* occ_body   = (const float*)d_in[5];
    const float* occ_face   = (const float*)d_in[6];
    float* out = (float*)d_out;

    (void)in_sizes; (void)n_in; (void)out_size;

    // 1) per-row nearest-zero distance (2 warps/row, 16 px/thread, 2x occupancy)
    row_dist_kernel<<<NB * IMH / 4, 256>>>((const uint4*)mask);
    // 2) Chebyshev DT column combine + 4B record pack (8 px/thread, SIMD bytes)
    col_pack_kernel<<<(int)(NPIX / 8 / 256), 256>>>((const uint4*)face_depth,
                                                    (const uint4*)edge_mask);
    // 3) fused sampling + fusion (4 queries/thread, 16 gathers in flight)
    fuse_kernel<<<(NB * NQ / 4) / 256, 256>>>(xy, z, occ_body, occ_face, out);
}